// round 16
// baseline (speedup 1.0000x reference)
#include <cuda_runtime.h>
#include <cuda_bf16.h>
#include <math.h>
#include <stdint.h>

typedef unsigned long long u64;

#define BDIM 128
#define LDIM 128
#define NNEI 6
#define FAA 39
#define FBB 10
#define FC 49
#define DD 200
#define D2 400
#define D3 600
#define RR 3
#define TTI 2
#define MBOND 256
#define NEGV -9e8f
#define NATOM (BDIM*LDIM)    /* 16384 */
#define NROWN (NATOM*NNEI)   /* 98304 */
#define KPAD 64
#define KP 224
#define KPW (KP/2)           /* 112 pairs: stride for D=200 activations */
#define LDPA 32              /* pairs stride for K=64 inputs */
#define NPAIR 100            /* live pairs for D=200 */
#define MOLSM_FLOATS (25600+128+200+200+128+128+128+200+200+600+600+32)

// ---------------- device scratch (static, zero-initialized) ----------------
__device__ float g_atomfeat[NATOM*DD];   // h fp32 (updated in place)
__device__ float g_cur[NATOM*DD];
__device__ float g_nei0[NROWN*DD];
__device__ float g_gi[NATOM*D3];
__device__ float g_gh[NATOM*D3];
__device__ float g_wtot[NATOM];
// packed activation planes (pads beyond NPAIR stay zero)
__device__ uint32_t g_apad_h[NATOM*LDPA],  g_apad_l[NATOM*LDPA];
__device__ uint32_t g_con_h[NROWN*LDPA],   g_con_l[NROWN*LDPA];
__device__ uint32_t g_h_h[NATOM*KPW],      g_h_l[NATOM*KPW];
__device__ uint32_t g_wsum_h[NATOM*KPW],   g_wsum_l[NATOM*KPW];
__device__ uint32_t g_ctx_h[NATOM*KPW],    g_ctx_l[NATOM*KPW];
// packed bf16-pair weights
__device__ uint32_t g_WT_atom_h[200*KPW],  g_WT_atom_l[200*KPW];
__device__ uint32_t g_WT_nei_h[200*KPW],   g_WT_nei_l[200*KPW];
__device__ uint32_t g_WT_att_h[3*200*KPW], g_WT_att_l[3*200*KPW];
__device__ uint32_t g_Wih_h[3*600*KPW],    g_Wih_l[3*600*KPW];
__device__ uint32_t g_Whh_h[3*600*KPW],    g_Whh_l[3*600*KPW];

// ---------------- helpers ----------------
__device__ __forceinline__ float warpsum(float v) {
    #pragma unroll
    for (int o = 16; o > 0; o >>= 1) v += __shfl_down_sync(0xffffffffu, v, o);
    return v;
}
__device__ __forceinline__ float warpall(float v) {
    #pragma unroll
    for (int o = 16; o > 0; o >>= 1) v += __shfl_xor_sync(0xffffffffu, v, o);
    return v;
}
__device__ __forceinline__ float lrelu(float x) { return x > 0.f ? x : 0.01f * x; }
__device__ __forceinline__ float eluf(float x)  { return x > 0.f ? x : expm1f(x); }
__device__ __forceinline__ float sigm(float x)  { return 1.f / (1.f + expf(-x)); }

__device__ __forceinline__ void split_bf16(float x, __nv_bfloat16& h, __nv_bfloat16& l) {
    h = __float2bfloat16_rn(x);
    l = __float2bfloat16_rn(x - __bfloat162float(h));
}
__device__ __forceinline__ uint32_t pack2(__nv_bfloat16 a, __nv_bfloat16 b) {
    __nv_bfloat162 p = __halves2bfloat162(a, b);
    return *reinterpret_cast<uint32_t*>(&p);
}
__device__ __forceinline__ void split_pair(float a, float b, uint32_t& hw, uint32_t& lw) {
    __nv_bfloat16 ha, la, hb, lb;
    split_bf16(a, ha, la); split_bf16(b, hb, lb);
    hw = pack2(ha, hb); lw = pack2(la, lb);
}

#define MMAB(c, a, b) \
    asm volatile("mma.sync.aligned.m16n8k16.row.col.f32.bf16.bf16.f32 " \
        "{%0,%1,%2,%3}, {%4,%5,%6,%7}, {%8,%9}, {%0,%1,%2,%3};" \
        : "+f"((c)[0]), "+f"((c)[1]), "+f"((c)[2]), "+f"((c)[3]) \
        : "r"((a)[0]), "r"((a)[1]), "r"((a)[2]), "r"((a)[3]), \
          "r"((b)[0]), "r"((b)[1]))

// =====================================================================
// Split-bf16 tensor GEMM, pre-packed A planes. BM=128 BN=128, prefetch.
// =====================================================================
template<int DUAL>
__global__ __launch_bounds__(256) void bfgemm_kernel(
    const uint32_t* __restrict__ Aph, const uint32_t* __restrict__ Apl, int ldp, int K,
    const uint32_t* __restrict__ WTh, const uint32_t* __restrict__ WTl,
    const float* __restrict__ bias,
    const float* __restrict__ rowscale,
    float* __restrict__ C, uint32_t* __restrict__ Cph, uint32_t* __restrict__ Cpl, int ldcp,
    int M, int Ntot, int act,
    const uint32_t* A2h, const uint32_t* A2l,
    const uint32_t* W2h, const uint32_t* W2l,
    const float* bias2, float* C2)
{
    if (DUAL && blockIdx.z == 1) {
        Aph = A2h; Apl = A2l; WTh = W2h; WTl = W2l; bias = bias2; C = C2;
    }

    __shared__ uint32_t APh[8][132], APl[8][132];
    __shared__ uint32_t BPh[8][136], BPl[8][136];

    const int tid = threadIdx.x;
    const int wid = tid >> 5;
    const int lane = tid & 31;
    const int gid = lane >> 2;
    const int tg = lane & 3;
    const int bm0 = blockIdx.x * 128;
    const int bn0 = blockIdx.y * 128;
    const int wm = (wid & 3) * 32;
    const int wn = (wid >> 2) * 64;

    const int a_r = tid >> 1, a_p4 = (tid & 1) << 2;
    const int b_r = tid >> 1, b_p4 = (tid & 1) << 2;

    float c[2][8][4];
    #pragma unroll
    for (int mt = 0; mt < 2; mt++)
        #pragma unroll
        for (int nt = 0; nt < 8; nt++)
            #pragma unroll
            for (int q = 0; q < 4; q++) c[mt][nt][q] = 0.f;

    const int nch = (K + 15) >> 4;

    uint4 avh, avl, bvh, bvl;
    {
        size_t aoff = (size_t)(bm0 + a_r) * ldp + a_p4;
        avh = *reinterpret_cast<const uint4*>(Aph + aoff);
        avl = *reinterpret_cast<const uint4*>(Apl + aoff);
        int n = bn0 + b_r;
        if (n < Ntot) {
            size_t off = (size_t)n * KPW + b_p4;
            bvh = *reinterpret_cast<const uint4*>(WTh + off);
            bvl = *reinterpret_cast<const uint4*>(WTl + off);
        } else { bvh = make_uint4(0u,0u,0u,0u); bvl = make_uint4(0u,0u,0u,0u); }
    }

    for (int chn = 0; chn < nch; chn++) {
        APh[a_p4 + 0][a_r] = avh.x; APh[a_p4 + 1][a_r] = avh.y;
        APh[a_p4 + 2][a_r] = avh.z; APh[a_p4 + 3][a_r] = avh.w;
        APl[a_p4 + 0][a_r] = avl.x; APl[a_p4 + 1][a_r] = avl.y;
        APl[a_p4 + 2][a_r] = avl.z; APl[a_p4 + 3][a_r] = avl.w;
        BPh[b_p4 + 0][b_r] = bvh.x; BPh[b_p4 + 1][b_r] = bvh.y;
        BPh[b_p4 + 2][b_r] = bvh.z; BPh[b_p4 + 3][b_r] = bvh.w;
        BPl[b_p4 + 0][b_r] = bvl.x; BPl[b_p4 + 1][b_r] = bvl.y;
        BPl[b_p4 + 2][b_r] = bvl.z; BPl[b_p4 + 3][b_r] = bvl.w;
        __syncthreads();

        if (chn + 1 < nch) {
            const int kp0 = (chn + 1) << 3;
            size_t aoff = (size_t)(bm0 + a_r) * ldp + kp0 + a_p4;
            avh = *reinterpret_cast<const uint4*>(Aph + aoff);
            avl = *reinterpret_cast<const uint4*>(Apl + aoff);
            int n = bn0 + b_r;
            if (n < Ntot) {
                size_t off = (size_t)n * KPW + kp0 + b_p4;
                bvh = *reinterpret_cast<const uint4*>(WTh + off);
                bvl = *reinterpret_cast<const uint4*>(WTl + off);
            } else { bvh = make_uint4(0u,0u,0u,0u); bvl = make_uint4(0u,0u,0u,0u); }
        }

        uint32_t ah[2][4], al[2][4];
        #pragma unroll
        for (int mt = 0; mt < 2; mt++) {
            int mr = wm + mt * 16;
            ah[mt][0] = APh[tg][mr + gid];
            ah[mt][1] = APh[tg][mr + gid + 8];
            ah[mt][2] = APh[tg + 4][mr + gid];
            ah[mt][3] = APh[tg + 4][mr + gid + 8];
            al[mt][0] = APl[tg][mr + gid];
            al[mt][1] = APl[tg][mr + gid + 8];
            al[mt][2] = APl[tg + 4][mr + gid];
            al[mt][3] = APl[tg + 4][mr + gid + 8];
        }
        #pragma unroll
        for (int nt = 0; nt < 8; nt++) {
            int nc = wn + nt * 8 + gid;
            uint32_t bh[2] = { BPh[tg][nc], BPh[tg + 4][nc] };
            uint32_t bl[2] = { BPl[tg][nc], BPl[tg + 4][nc] };
            #pragma unroll
            for (int mt = 0; mt < 2; mt++) {
                MMAB(c[mt][nt], ah[mt], bh);
                MMAB(c[mt][nt], ah[mt], bl);
                MMAB(c[mt][nt], al[mt], bh);
            }
        }
        __syncthreads();
    }

    #pragma unroll
    for (int mt = 0; mt < 2; mt++) {
        #pragma unroll
        for (int half = 0; half < 2; half++) {
            int m = bm0 + wm + mt * 16 + gid + half * 8;
            float rs = rowscale ? rowscale[m] : 1.f;
            #pragma unroll
            for (int nt = 0; nt < 8; nt++) {
                int n = bn0 + wn + nt * 8 + 2 * tg;
                if (n >= Ntot) continue;
                float v0 = c[mt][nt][half * 2 + 0] + rs * (bias ? bias[n] : 0.f);
                float v1 = c[mt][nt][half * 2 + 1] + rs * (bias ? bias[n + 1] : 0.f);
                if (act == 1) { v0 = lrelu(v0); v1 = lrelu(v1); }
                else if (act == 2) { v0 = eluf(v0); v1 = eluf(v1); }
                if (C) {
                    float* crow = C + (size_t)m * Ntot;
                    crow[n] = v0; crow[n + 1] = v1;
                }
                if (Cph) {
                    uint32_t hw, lw;
                    split_pair(v0, v1, hw, lw);
                    size_t po = (size_t)m * ldcp + (n >> 1);
                    Cph[po] = hw; Cpl[po] = lw;
                }
            }
        }
    }
}

// ---------------- fused weight prep: Wih + Whh pads ----------------
__global__ void prep_pad2(const float* __restrict__ in1,
                          uint32_t* __restrict__ o1h, uint32_t* __restrict__ o1l,
                          const float* __restrict__ in2,
                          uint32_t* __restrict__ o2h, uint32_t* __restrict__ o2l)
{
    const int T = 1800 * KPW;
    int i = blockIdx.x * 256 + threadIdx.x;
    if (i >= 2 * T) return;
    const float* in; uint32_t *oh, *ol; int j;
    if (i < T) { in = in1; oh = o1h; ol = o1l; j = i; }
    else       { in = in2; oh = o2h; ol = o2l; j = i - T; }
    int n = j / KPW, kp = j - n * KPW;
    int k = kp << 1;
    float x0 = (k < DD) ? in[(size_t)n * DD + k] : 0.f;
    float x1 = (k + 1 < DD) ? in[(size_t)n * DD + k + 1] : 0.f;
    uint32_t hw, lw;
    split_pair(x0, x1, hw, lw);
    oh[j] = hw; ol[j] = lw;
}

// ---------------- fused weight prep: atom/nei/att transposes ----------------
__global__ void prep_trans3(const float* __restrict__ Wa,
                            uint32_t* __restrict__ ah, uint32_t* __restrict__ al,
                            const float* __restrict__ Wn,
                            uint32_t* __restrict__ nh, uint32_t* __restrict__ nl,
                            const float* __restrict__ Wt,
                            uint32_t* __restrict__ th, uint32_t* __restrict__ tl)
{
    const int S = 200 * KPW;
    int i = blockIdx.x * 256 + threadIdx.x;
    if (i >= 5 * S) return;
    const float* in; uint32_t *oh, *ol; int j, K, r = 0;
    if (i < S)          { in = Wa; oh = ah; ol = al; j = i; K = FAA; }
    else if (i < 2 * S) { in = Wn; oh = nh; ol = nl; j = i - S; K = FC; }
    else                { in = Wt; oh = th; ol = tl; j = i - 2 * S; K = DD;
                          r = j / S; j -= r * S; }
    int kp = j % KPW;
    int n = j / KPW;
    int k = kp << 1;
    float x0 = (k < K) ? in[((size_t)r * K + k) * DD + n] : 0.f;
    float x1 = (k + 1 < K) ? in[((size_t)r * K + k + 1) * DD + n] : 0.f;
    uint32_t hw, lw;
    split_pair(x0, x1, hw, lw);
    int outoff = (i < 2 * S) ? j : (r * S + j);
    oh[outoff] = hw; ol[outoff] = lw;
}

// ---------------- pad atom_list -> packed [NATOM, LDPA] ----------------
__global__ void pad_atom_kernel(const float* __restrict__ atom_list,
                                uint32_t* __restrict__ outh, uint32_t* __restrict__ outl)
{
    int i = blockIdx.x * blockDim.x + threadIdx.x;
    if (i >= NATOM * LDPA) return;
    int row = i / LDPA;
    int p = i - row * LDPA;
    int k = p << 1;
    float x0 = (k < FAA) ? atom_list[row * FAA + k] : 0.f;
    float x1 = (k + 1 < FAA) ? atom_list[row * FAA + k + 1] : 0.f;
    uint32_t hw, lw;
    split_pair(x0, x1, hw, lw);
    outh[i] = hw; outl[i] = lw;
}

// ---------------- build concat packed [NROWN, LDPA] ----------------
__global__ void build_concat(const float* __restrict__ atom_list,
                             const float* __restrict__ bond_list,
                             const int* __restrict__ adeg,
                             const int* __restrict__ bdeg,
                             uint32_t* __restrict__ outh, uint32_t* __restrict__ outl)
{
    int i = blockIdx.x * blockDim.x + threadIdx.x;
    if (i >= NROWN * LDPA) return;
    int row = i / LDPA;
    int p = i - row * LDPA;
    int b = row / (LDIM * NNEI);
    int a = adeg[row];
    int bd = bdeg[row];
    const float* arow = atom_list + ((size_t)b * LDIM + a) * FAA;
    const float* brow = bond_list + ((size_t)b * MBOND + bd) * FBB;
    float v[2];
    #pragma unroll
    for (int q = 0; q < 2; q++) {
        int f = 2 * p + q;
        float x = 0.f;
        if (f < FAA) x = arow[f];
        else if (f < FC) x = brow[f - FAA];
        v[q] = x;
    }
    uint32_t hw, lw;
    split_pair(v[0], v[1], hw, lw);
    outh[i] = hw; outl[i] = lw;
}

// ---------------- attention: warp-per-atom, packed wsum out ----------------
#define CHP 4
__global__ void ctx_kernel(const float* __restrict__ cur,
                           const float* __restrict__ neiBuf,
                           const int* __restrict__ adeg,
                           const float* __restrict__ Wal,
                           const float* __restrict__ bal,
                           uint32_t* __restrict__ wsh, uint32_t* __restrict__ wsl,
                           float* __restrict__ wtot,
                           int firstRound)
{
    const int tid = threadIdx.x;
    const int wid = tid >> 5;
    const int lane = tid & 31;
    const int atom = blockIdx.x * 8 + wid;
    const int b = atom / LDIM;

    int myidx = (lane < NNEI) ? adeg[atom * NNEI + lane] : 0;
    int idx[NNEI];
    #pragma unroll
    for (int n = 0; n < NNEI; n++) idx[n] = __shfl_sync(0xffffffffu, myidx, n);

    const float* neirow[NNEI];
    #pragma unroll
    for (int n = 0; n < NNEI; n++)
        neirow[n] = firstRound ? (neiBuf + ((size_t)atom * NNEI + n) * DD)
                               : (cur + ((size_t)(b * LDIM + idx[n])) * DD);
    const float* currow = cur + (size_t)atom * DD;

    float2 curv[CHP], neiv[NNEI][CHP], w1v[CHP], w2v[CHP];
    #pragma unroll
    for (int i = 0; i < CHP; i++) {
        int p = lane + 32 * i;
        bool ok = p < NPAIR;
        int d = 2 * p;
        curv[i] = ok ? *reinterpret_cast<const float2*>(currow + d) : make_float2(0.f, 0.f);
        w1v[i]  = ok ? *reinterpret_cast<const float2*>(Wal + d) : make_float2(0.f, 0.f);
        w2v[i]  = ok ? *reinterpret_cast<const float2*>(Wal + DD + d) : make_float2(0.f, 0.f);
        #pragma unroll
        for (int n = 0; n < NNEI; n++)
            neiv[n][i] = ok ? *reinterpret_cast<const float2*>(neirow[n] + d)
                            : make_float2(0.f, 0.f);
    }

    float pc = 0.f;
    #pragma unroll
    for (int i = 0; i < CHP; i++) pc += w1v[i].x * curv[i].x + w1v[i].y * curv[i].y;
    pc = warpall(pc);
    float pn[NNEI];
    #pragma unroll
    for (int n = 0; n < NNEI; n++) {
        float p = 0.f;
        #pragma unroll
        for (int i = 0; i < CHP; i++) p += w2v[i].x * neiv[n][i].x + w2v[i].y * neiv[n][i].y;
        pn[n] = warpall(p);
    }

    float bb = bal[0];
    float sc[NNEI], msk[NNEI];
    float mx = -1e30f;
    #pragma unroll
    for (int n = 0; n < NNEI; n++) {
        float a = lrelu(pc + pn[n] + bb);
        bool pad = (idx[n] == LDIM - 1);
        msk[n] = pad ? 0.f : 1.f;
        a += pad ? NEGV : 0.f;
        sc[n] = a;
        mx = fmaxf(mx, a);
    }
    float sum = 0.f;
    float w[NNEI];
    #pragma unroll
    for (int n = 0; n < NNEI; n++) { w[n] = expf(sc[n] - mx); sum += w[n]; }
    float inv = 1.f / sum;
    float wt = 0.f;
    #pragma unroll
    for (int n = 0; n < NNEI; n++) { w[n] = w[n] * inv * msk[n]; wt += w[n]; }

    #pragma unroll
    for (int i = 0; i < CHP; i++) {
        int p = lane + 32 * i;
        if (p < NPAIR) {
            float s0 = 0.f, s1 = 0.f;
            #pragma unroll
            for (int n = 0; n < NNEI; n++) {
                s0 += w[n] * neiv[n][i].x;
                s1 += w[n] * neiv[n][i].y;
            }
            uint32_t hw, lw;
            split_pair(s0, s1, hw, lw);
            size_t po = (size_t)atom * KPW + p;
            wsh[po] = hw; wsl[po] = lw;
        }
    }
    if (lane == 0) wtot[atom] = wt;
}

// ---------------- GRU combine (atom rounds) ----------------
__global__ void gru_combine(const float* __restrict__ gi, const float* __restrict__ gh,
                            const float* __restrict__ h,
                            float* __restrict__ hOut,
                            uint32_t* __restrict__ hPh, uint32_t* __restrict__ hPl,
                            float* __restrict__ actOut, int Mrows)
{
    int i = blockIdx.x * blockDim.x + threadIdx.x;
    if (i >= Mrows * NPAIR) return;
    int m = i / NPAIR;
    int p = i - m * NPAIR;
    int d = 2 * p;
    const float* gim = gi + (size_t)m * D3;
    const float* ghm = gh + (size_t)m * D3;
    float hn[2];
    #pragma unroll
    for (int q = 0; q < 2; q++) {
        int dq = d + q;
        float r = sigm(gim[dq] + ghm[dq]);
        float z = sigm(gim[DD + dq] + ghm[DD + dq]);
        float nv = tanhf(gim[2 * DD + dq] + r * ghm[2 * DD + dq]);
        float hv = h[(size_t)m * DD + dq];
        hn[q] = (1.f - z) * nv + z * hv;
        hOut[(size_t)m * DD + dq] = hn[q];
        actOut[(size_t)m * DD + dq] = hn[q] > 0.f ? hn[q] : 0.f;
    }
    uint32_t hw, lw;
    split_pair(hn[0], hn[1], hw, lw);
    size_t po = (size_t)m * KPW + p;
    hPh[po] = hw; hPl[po] = lw;
}

// =====================================================================
// Fused mol phase: one block per molecule, everything in smem.
// =====================================================================
__global__ void mol_fused_kernel(
    const float* __restrict__ cur, const float* __restrict__ amask,
    const float* __restrict__ Wma, const float* __restrict__ bma,
    const float* __restrict__ Wmatt, const float* __restrict__ bmatt,
    const float* __restrict__ mWih, const float* __restrict__ mWhh,
    const float* __restrict__ mbih, const float* __restrict__ mbhh,
    const float* __restrict__ Wm, const float* __restrict__ bm,
    const float* __restrict__ Wo, const float* __restrict__ bo,
    float* __restrict__ out)
{
    extern __shared__ float sm[];
    float* curS   = sm;                  // 25600
    float* amaskS = curS + 25600;        // 128
    float* molS   = amaskS + 128;        // 200
    float* actS   = molS + 200;          // 200
    float* s2S    = actS + 200;          // 128
    float* scS    = s2S + 128;           // 128
    float* wSS    = scS + 128;           // 128
    float* mwsumS = wSS + 128;           // 200
    float* mctxS  = mwsumS + 200;        // 200
    float* giS    = mctxS + 200;         // 600 (reused as feat[400])
    float* ghS    = giS + 600;           // 600
    float* redS   = ghS + 600;           // 32

    const int b = blockIdx.x;
    const int tid = threadIdx.x;
    const int wid = tid >> 5;
    const int lane = tid & 31;

    const float* curG = cur + (size_t)b * LDIM * DD;
    for (int i = tid; i < LDIM * DD / 4; i += 256)
        reinterpret_cast<float4*>(curS)[i] = reinterpret_cast<const float4*>(curG)[i];
    if (tid < LDIM) amaskS[tid] = amask[b * LDIM + tid];
    __syncthreads();

    // mol = masked column sum; act = relu(mol)
    for (int d = tid; d < DD; d += 256) {
        float s = 0.f;
        for (int l = 0; l < LDIM; l++) s += curS[l * DD + d] * amaskS[l];
        molS[d] = s;
        actS[d] = s > 0.f ? s : 0.f;
    }
    // s2 per atom
    for (int l = wid; l < LDIM; l += 8) {
        float p = 0.f;
        for (int d = lane; d < DD; d += 32) p += curS[l * DD + d] * Wma[DD + d];
        p = warpsum(p);
        if (lane == 0) s2S[l] = p;
    }
    __syncthreads();

    for (int t = 0; t < TTI; t++) {
        // s1 = act . Wma[0:D]
        if (tid == 0) redS[0] = 0.f;
        __syncthreads();
        float p = 0.f;
        for (int d = tid; d < DD; d += 256) p += actS[d] * Wma[d];
        p = warpsum(p);
        if (lane == 0) atomicAdd(&redS[0], p);
        __syncthreads();
        float s1 = redS[0];

        if (tid < LDIM) {
            float a = lrelu(s1 + s2S[tid] + bma[0]);
            if (amaskS[tid] == 0.f) a += NEGV;
            scS[tid] = a;
        }
        __syncthreads();
        if (tid < LDIM) {
            float mx = -1e30f;
            for (int l = 0; l < LDIM; l++) mx = fmaxf(mx, scS[l]);
            float sum = 0.f;
            for (int l = 0; l < LDIM; l++) sum += expf(scS[l] - mx);
            wSS[tid] = expf(scS[tid] - mx) / sum * amaskS[tid];
        }
        __syncthreads();
        if (tid == 0) {
            float wt = 0.f;
            for (int l = 0; l < LDIM; l++) wt += wSS[l];
            redS[1] = wt;
        }
        // mwsum
        for (int d = tid; d < DD; d += 256) {
            float s = 0.f;
            for (int l = 0; l < LDIM; l++) s += wSS[l] * curS[l * DD + d];
            mwsumS[d] = s;
        }
        __syncthreads();
        float wtot = redS[1];
        // mctx = elu(mwsum @ Wmatt + wtot*bias)
        for (int j = tid; j < DD; j += 256) {
            float v = wtot * bmatt[j];
            for (int in = 0; in < DD; in++) v += mwsumS[in] * Wmatt[in * DD + j];
            mctxS[j] = eluf(v);
        }
        __syncthreads();
        // gi/gh: warp-per-row GEMVs
        for (int n = wid; n < D3; n += 8) {
            float pi = 0.f, ph = 0.f;
            const float* wi = mWih + (size_t)n * DD;
            const float* wh = mWhh + (size_t)n * DD;
            for (int k = lane; k < DD; k += 32) {
                pi += mctxS[k] * wi[k];
                ph += molS[k] * wh[k];
            }
            pi = warpsum(pi); ph = warpsum(ph);
            if (lane == 0) { giS[n] = pi + mbih[n]; ghS[n] = ph + mbhh[n]; }
        }
        __syncthreads();
        // GRU
        if (tid < DD) {
            int d = tid;
            float r = sigm(giS[d] + ghS[d]);
            float z = sigm(giS[DD + d] + ghS[DD + d]);
            float nv = tanhf(giS[2 * DD + d] + r * ghS[2 * DD + d]);
            float hn = (1.f - z) * nv + z * molS[d];
            molS[d] = hn;
            actS[d] = hn > 0.f ? hn : 0.f;
        }
        __syncthreads();
    }

    // final projection
    float* featS = giS;
    for (int j = tid; j < D2; j += 256)
        featS[j] = (j < DD) ? molS[j] : (molS[j - DD] + (float)(RR - 2));
    if (tid == 0) redS[2] = 0.f;
    __syncthreads();
    float p2 = 0.f;
    for (int d = tid; d < DD; d += 256) {
        float s = bm[d];
        for (int j = 0; j < D2; j++) s += featS[j] * Wm[j * DD + d];
        p2 += s * Wo[d];
    }
    p2 = warpsum(p2);
    if (lane == 0) atomicAdd(&redS[2], p2);
    __syncthreads();
    if (tid == 0) out[b] = redS[2] + bo[0];
}

// ---------------- host-side dispatch ----------------
static void tgemm(const uint32_t* Aph, const uint32_t* Apl, int ldp, int K,
                  const uint32_t* WTh, const uint32_t* WTl,
                  const float* bias, const float* rowscale,
                  float* C, uint32_t* Cph, uint32_t* Cpl,
                  int M, int Ntot, int act)
{
    dim3 g(M / 128, (Ntot + 127) / 128, 1);
    bfgemm_kernel<0><<<g, 256>>>(Aph, Apl, ldp, K, WTh, WTl, bias, rowscale,
                                 C, Cph, Cpl, KPW, M, Ntot, act,
                                 nullptr, nullptr, nullptr, nullptr, nullptr, nullptr);
}

static void tgemm_dual(const uint32_t* A1h, const uint32_t* A1l,
                       const uint32_t* W1h, const uint32_t* W1l,
                       const float* bias1, float* C1,
                       const uint32_t* A2h, const uint32_t* A2l,
                       const uint32_t* W2h, const uint32_t* W2l,
                       const float* bias2, float* C2,
                       int M, int Ntot)
{
    dim3 g(M / 128, (Ntot + 127) / 128, 2);
    bfgemm_kernel<1><<<g, 256>>>(A1h, A1l, KPW, DD, W1h, W1l, bias1, nullptr,
                                 C1, nullptr, nullptr, KPW, M, Ntot, 0,
                                 A2h, A2l, W2h, W2l, bias2, C2);
}

extern "C" void kernel_launch(void* const* d_in, const int* in_sizes, int n_in,
                              void* d_out, int out_size)
{
    const float* atom_list   = (const float*)d_in[0];
    const float* bond_list   = (const float*)d_in[1];
    const int*   adeg        = (const int*)d_in[2];
    const int*   bdeg        = (const int*)d_in[3];
    const float* amask       = (const float*)d_in[4];
    const float* W_atom      = (const float*)d_in[5];
    const float* b_atom      = (const float*)d_in[6];
    const float* W_nei       = (const float*)d_in[7];
    const float* b_nei       = (const float*)d_in[8];
    const float* W_align     = (const float*)d_in[9];
    const float* b_align     = (const float*)d_in[10];
    const float* W_attend    = (const float*)d_in[11];
    const float* b_attend    = (const float*)d_in[12];
    const float* Wih         = (const float*)d_in[13];
    const float* Whh         = (const float*)d_in[14];
    const float* bih         = (const float*)d_in[15];
    const float* bhh         = (const float*)d_in[16];
    const float* W_mol_align = (const float*)d_in[17];
    const float* b_mol_align = (const float*)d_in[18];
    const float* W_mol_att   = (const float*)d_in[19];
    const float* b_mol_att   = (const float*)d_in[20];
    const float* mWih        = (const float*)d_in[21];
    const float* mWhh        = (const float*)d_in[22];
    const float* mbih        = (const float*)d_in[23];
    const float* mbhh        = (const float*)d_in[24];
    const float* W_metric    = (const float*)d_in[25];
    const float* b_metric    = (const float*)d_in[26];
    const float* W_out       = (const float*)d_in[27];
    const float* b_out       = (const float*)d_in[28];

    float *atomfeat, *cur, *nei0, *gi, *gh, *wtot;
    uint32_t *apad_h, *apad_l, *con_h, *con_l, *h_h, *h_l, *wsum_h, *wsum_l;
    uint32_t *ctx_h, *ctx_l;
    uint32_t *WT_atom_h, *WT_atom_l, *WT_nei_h, *WT_nei_l, *WT_att_h, *WT_att_l;
    uint32_t *Wih_h, *Wih_l, *Whh_h, *Whh_l;
    cudaGetSymbolAddress((void**)&atomfeat, g_atomfeat);
    cudaGetSymbolAddress((void**)&cur, g_cur);
    cudaGetSymbolAddress((void**)&nei0, g_nei0);
    cudaGetSymbolAddress((void**)&gi, g_gi);
    cudaGetSymbolAddress((void**)&gh, g_gh);
    cudaGetSymbolAddress((void**)&wtot, g_wtot);
    cudaGetSymbolAddress((void**)&apad_h, g_apad_h);
    cudaGetSymbolAddress((void**)&apad_l, g_apad_l);
    cudaGetSymbolAddress((void**)&con_h, g_con_h);
    cudaGetSymbolAddress((void**)&con_l, g_con_l);
    cudaGetSymbolAddress((void**)&h_h, g_h_h);
    cudaGetSymbolAddress((void**)&h_l, g_h_l);
    cudaGetSymbolAddress((void**)&wsum_h, g_wsum_h);
    cudaGetSymbolAddress((void**)&wsum_l, g_wsum_l);
    cudaGetSymbolAddress((void**)&ctx_h, g_ctx_h);
    cudaGetSymbolAddress((void**)&ctx_l, g_ctx_l);
    cudaGetSymbolAddress((void**)&WT_atom_h, g_WT_atom_h);
    cudaGetSymbolAddress((void**)&WT_atom_l, g_WT_atom_l);
    cudaGetSymbolAddress((void**)&WT_nei_h, g_WT_nei_h);
    cudaGetSymbolAddress((void**)&WT_nei_l, g_WT_nei_l);
    cudaGetSymbolAddress((void**)&WT_att_h, g_WT_att_h);
    cudaGetSymbolAddress((void**)&WT_att_l, g_WT_att_l);
    cudaGetSymbolAddress((void**)&Wih_h, g_Wih_h);
    cudaGetSymbolAddress((void**)&Wih_l, g_Wih_l);
    cudaGetSymbolAddress((void**)&Whh_h, g_Whh_h);
    cudaGetSymbolAddress((void**)&Whh_l, g_Whh_l);

    float* h = atomfeat;

    // enable large dynamic smem for the fused mol kernel (idempotent)
    cudaFuncSetAttribute(mol_fused_kernel,
                         cudaFuncAttributeMaxDynamicSharedMemorySize,
                         MOLSM_FLOATS * sizeof(float));

    // 0) weight prep (2 fused kernels)
    {
        int n = 2 * 1800 * KPW;
        prep_pad2<<<(n + 255) / 256, 256>>>(Wih, Wih_h, Wih_l, Whh, Whh_h, Whh_l);
        n = 5 * 200 * KPW;
        prep_trans3<<<(n + 255) / 256, 256>>>(W_atom, WT_atom_h, WT_atom_l,
                                              W_nei, WT_nei_h, WT_nei_l,
                                              W_attend, WT_att_h, WT_att_l);
    }

    // 1) atom_feature = lrelu(atom_list @ W_atom + b_atom)
    pad_atom_kernel<<<(NATOM * LDPA + 255) / 256, 256>>>(atom_list, apad_h, apad_l);
    tgemm(apad_h, apad_l, LDPA, KPAD, WT_atom_h, WT_atom_l, b_atom, nullptr,
          atomfeat, h_h, h_l, NATOM, DD, 1);

    // 2) nei0 = lrelu(concat @ W_nei + b_nei)
    build_concat<<<(NROWN * LDPA + 255) / 256, 256>>>(atom_list, bond_list, adeg, bdeg,
                                                      con_h, con_l);
    tgemm(con_h, con_l, LDPA, KPAD, WT_nei_h, WT_nei_l, b_nei, nullptr,
          nei0, nullptr, nullptr, NROWN, DD, 1);

    // 3) atom GRU rounds
    for (int r = 0; r < RR; r++) {
        const float* curp = (r == 0) ? atomfeat : cur;
        ctx_kernel<<<NATOM / 8, 256>>>(curp, (r == 0) ? nei0 : nullptr, adeg,
                                       W_align + (size_t)r * D2, b_align + r,
                                       wsum_h, wsum_l, wtot, (r == 0) ? 1 : 0);
        tgemm(wsum_h, wsum_l, KPW, DD,
              WT_att_h + (size_t)r * 200 * KPW, WT_att_l + (size_t)r * 200 * KPW,
              b_attend + r * DD, wtot, nullptr, ctx_h, ctx_l, NATOM, DD, 2);
        tgemm_dual(ctx_h, ctx_l, Wih_h + (size_t)r * D3 * KPW, Wih_l + (size_t)r * D3 * KPW,
                   bih + r * D3, gi,
                   h_h, h_l, Whh_h + (size_t)r * D3 * KPW, Whh_l + (size_t)r * D3 * KPW,
                   bhh + r * D3, gh, NATOM, D3);
        gru_combine<<<(NATOM * NPAIR + 255) / 256, 256>>>(gi, gh, h, h, h_h, h_l, cur, NATOM);
    }

    // 4+5) fused mol phase + final projection
    mol_fused_kernel<<<BDIM, 256, MOLSM_FLOATS * sizeof(float)>>>(
        cur, amask, W_mol_align, b_mol_align, W_mol_att, b_mol_att,
        mWih, mWhh, mbih, mbhh, W_metric, b_metric, W_out, b_out, (float*)d_out);
}